// round 1
// baseline (speedup 1.0000x reference)
#include <cuda_runtime.h>

// ============================================================================
// LSTM_3040836845939: 4-layer LSTM (T=262144, H=90) + FC(2) + softmax + argmax
//
// Strategy: software-pipelined persistent kernel.
//  - blocks 0..3  : one recurrent CTA per layer. W_hh rows in registers
//                   (float2 pairs, fma.rn.f32x2), h in smem, c in registers of
//                   threads 0..89. Reads precomputed x_proj from global.
//  - blocks 4..63 : worker CTAs pulling (layer, chunk) GEMM tasks off an atomic
//                   queue; compute x_proj[l][chunk] = h[l-1][chunk] @ W_ih^T + b
//                   as soon as h[l-1][chunk] is flagged complete.
//  - chunk-granular flag synchronization through L2 (__ldcg/__stcg + fences).
//  - separate fully-parallel FC/softmax/argmax kernel at the end.
// ============================================================================

#define T_MAX    262144
#define H90      90
#define HP       92            // H padded to multiple of 4 (float4 smem reads)
#define G4       360           // 4*H gate rows
#define NL       4
#define CH       512           // timesteps per pipeline chunk
#define NCHMAX   (T_MAX / CH)  // 512
#define NBLK     64            // must be <= SM count for co-residency
#define NTHREADS 384

// -------- static device scratch (allocation-free per harness rules) --------
__device__ float g_xp[NL][(size_t)T_MAX * G4];   // x_proj per layer  (1.51 GB)
__device__ float g_h [NL][(size_t)T_MAX * H90];  // h outputs per layer (377 MB)
__device__ int   g_hdone [NL][NCHMAX];
__device__ int   g_xpdone[NL][NCHMAX];
__device__ int   g_ctr;

// -------- packed fp32x2 FMA (Blackwell FFMA2) --------
__device__ __forceinline__ float2 ffma2(float2 a, float2 b, float2 c) {
#if defined(__CUDA_ARCH__) && (__CUDA_ARCH__ >= 1000)
    unsigned long long ua = *reinterpret_cast<unsigned long long*>(&a);
    unsigned long long ub = *reinterpret_cast<unsigned long long*>(&b);
    unsigned long long uc = *reinterpret_cast<unsigned long long*>(&c);
    unsigned long long ud;
    asm("fma.rn.f32x2 %0, %1, %2, %3;" : "=l"(ud) : "l"(ua), "l"(ub), "l"(uc));
    return *reinterpret_cast<float2*>(&ud);
#else
    return make_float2(fmaf(a.x, b.x, c.x), fmaf(a.y, b.y, c.y));
#endif
}

__device__ __forceinline__ float sigf(float x) {
    // 1/(1+e^-x); saturates correctly at +-inf
    return __fdividef(1.0f, 1.0f + __expf(-x));
}
__device__ __forceinline__ float tanhfast(float x) {
    // 1 - 2/(e^{2x}+1); saturates correctly at +-inf
    return 1.0f - __fdividef(2.0f, __expf(2.0f * x) + 1.0f);
}

// -------- flag reset (must run before lstm_main on every graph replay) -----
__global__ void init_k() {
    int i = blockIdx.x * blockDim.x + threadIdx.x;
    if (i == 0) g_ctr = 0;
    if (i < NL * NCHMAX) {
        ((int*)g_hdone)[i]  = 0;
        ((int*)g_xpdone)[i] = 0;
    }
}

// ============================================================================
// main persistent kernel
// ============================================================================
__global__ void __launch_bounds__(NTHREADS, 1) lstm_main(
    const float* __restrict__ x,
    const float* __restrict__ h0,
    const float* __restrict__ c0,
    const float* __restrict__ wih0,
    const float* __restrict__ wih1,
    const float* __restrict__ wih2,
    const float* __restrict__ wih3,
    const float* __restrict__ whh,
    const float* __restrict__ bih,
    const float* __restrict__ bhh,
    int T)
{
    const int tid = threadIdx.x;
    const int blk = blockIdx.x;
    const int NCH = (T + CH - 1) / CH;

    __shared__ __align__(16) float shA[HP];   // h vector / staging buffer 0
    __shared__ __align__(16) float shB[HP];   // staging buffer 1 (workers)
    __shared__ float shG[G4];                 // gate pre-activations
    __shared__ int   s_task;

    if (blk < NL) {
        // ---------------- recurrent CTA for layer l ----------------
        const int  l   = blk;
        const bool act = (tid < G4);

        // W_hh row for this thread's gate-output, padded to 92 with zeros
        float2 w[HP / 2];
        #pragma unroll
        for (int p = 0; p < HP / 2; p++) {
            float a = 0.f, b = 0.f;
            const int k2 = 2 * p;
            if (act) {
                const float* wr = &whh[((size_t)l * G4 + tid) * H90];
                if (k2     < H90) a = wr[k2];
                if (k2 + 1 < H90) b = wr[k2 + 1];
            }
            w[p] = make_float2(a, b);
        }
        float c = 0.f;
        if (tid < H90)               { shA[tid] = h0[l * H90 + tid]; c = c0[l * H90 + tid]; }
        if (tid >= H90 && tid < HP)  shA[tid] = 0.f;
        __syncthreads();

        float* xp_l = g_xp[l];
        float* h_l  = g_h[l];

        for (int k = 0; k < NCH; k++) {
            if (tid == 0) {
                while (*(volatile int*)&g_xpdone[l][k] == 0) __nanosleep(128);
                __threadfence();
            }
            __syncthreads();
            const int t0   = k * CH;
            const int rows = min(CH, T - t0);

            float xpc = act ? __ldcg(&xp_l[(size_t)t0 * G4 + tid]) : 0.f;
            for (int s = 0; s < rows; s++) {
                // prefetch next step's x_proj (within chunk only: data guaranteed)
                float xpn = (act && (s + 1 < rows))
                          ? __ldcg(&xp_l[(size_t)(t0 + s + 1) * G4 + tid]) : 0.f;

                // gate pre-activation: dot(W_hh[o,:], h) + x_proj (bias folded in)
                float2 a0 = make_float2(0.f, 0.f), a1 = a0;
                #pragma unroll
                for (int p = 0; p < HP / 4; p++) {
                    const float4 hv = *(const float4*)&shA[4 * p];
                    a0 = ffma2(w[2 * p],     make_float2(hv.x, hv.y), a0);
                    a1 = ffma2(w[2 * p + 1], make_float2(hv.z, hv.w), a1);
                }
                const float gv = (a0.x + a0.y) + (a1.x + a1.y) + xpc;
                if (act) shG[tid] = gv;
                __syncthreads();

                if (tid < H90) {
                    const float gi = sigf(shG[tid]);
                    const float gf = sigf(shG[H90 + tid]);
                    const float gg = tanhfast(shG[2 * H90 + tid]);
                    const float go = sigf(shG[3 * H90 + tid]);
                    c = gf * c + gi * gg;
                    const float hv = go * tanhfast(c);
                    shA[tid] = hv;
                    __stcg(&h_l[(size_t)(t0 + s) * H90 + tid], hv);
                }
                __syncthreads();
                xpc = xpn;
            }
            if (tid == 0) {                 // stores ordered by last __syncthreads
                __threadfence();
                *(volatile int*)&g_hdone[l][k] = 1;
            }
        }
    } else {
        // ---------------- worker CTA: x_proj GEMM task pool ----------------
        const int total = NL * NCH;
        while (true) {
            if (tid == 0) s_task = atomicAdd(&g_ctr, 1);
            __syncthreads();
            const int task = s_task;
            __syncthreads();
            if (task >= total) break;
            const int k  = task >> 2;
            const int l  = task & 3;
            const int t0 = k * CH;
            const int rows = min(CH, T - t0);

            if (l == 0) {
                // layer 0: x_proj0[t] = W_ih0 @ x_t + b  (in_dim = 6)
                float2 w0 = make_float2(0, 0), w1 = w0, w2 = w0;
                float bias = 0.f;
                if (tid < G4) {
                    const float* wr = &wih0[tid * 6];
                    w0 = make_float2(wr[0], wr[1]);
                    w1 = make_float2(wr[2], wr[3]);
                    w2 = make_float2(wr[4], wr[5]);
                    bias = bih[tid] + bhh[tid];
                }
                if (tid < 3) ((float2*)shA)[tid] = ((const float2*)&x[(size_t)t0 * 6])[tid];
                __syncthreads();
                for (int s = 0; s < rows; s++) {
                    float* cur = (s & 1) ? shB : shA;
                    float* nxt = (s & 1) ? shA : shB;
                    if ((s + 1 < rows) && tid < 3)
                        ((float2*)nxt)[tid] = ((const float2*)&x[(size_t)(t0 + s + 1) * 6])[tid];
                    const float2* xb = (const float2*)cur;
                    float2 a = ffma2(w0, xb[0], make_float2(0, 0));
                    a = ffma2(w1, xb[1], a);
                    a = ffma2(w2, xb[2], a);
                    const float v = a.x + a.y + bias;
                    if (tid < G4) __stcg(&g_xp[0][(size_t)(t0 + s) * G4 + tid], v);
                    __syncthreads();
                }
            } else {
                // layers 1..3: x_proj[l][t] = W_ih[l] @ h[l-1][t] + b
                const float* wih = (l == 1) ? wih1 : ((l == 2) ? wih2 : wih3);
                float2 w[HP / 2];
                float bias = 0.f;
                #pragma unroll
                for (int p = 0; p < HP / 2; p++) {
                    float a = 0.f, b = 0.f;
                    const int k2 = 2 * p;
                    if (tid < G4) {
                        const float* wr = &wih[(size_t)tid * H90];
                        if (k2     < H90) a = wr[k2];
                        if (k2 + 1 < H90) b = wr[k2 + 1];
                    }
                    w[p] = make_float2(a, b);
                }
                if (tid < G4) bias = bih[l * G4 + tid] + bhh[l * G4 + tid];
                const float* hsrc = g_h[l - 1];

                if (tid == 0) {
                    while (*(volatile int*)&g_hdone[l - 1][k] == 0) __nanosleep(256);
                    __threadfence();
                }
                __syncthreads();
                if (tid < H90) shA[tid] = __ldcg(&hsrc[(size_t)t0 * H90 + tid]);
                if (tid >= H90 && tid < HP) { shA[tid] = 0.f; shB[tid] = 0.f; }
                __syncthreads();

                float* xp_out = g_xp[l];
                for (int s = 0; s < rows; s++) {
                    float* cur = (s & 1) ? shB : shA;
                    float* nxt = (s & 1) ? shA : shB;
                    if ((s + 1 < rows) && tid < H90)
                        nxt[tid] = __ldcg(&hsrc[(size_t)(t0 + s + 1) * H90 + tid]);
                    float2 a0 = make_float2(0, 0), a1 = a0;
                    #pragma unroll
                    for (int p = 0; p < HP / 4; p++) {
                        const float4 hv = *(const float4*)&cur[4 * p];
                        a0 = ffma2(w[2 * p],     make_float2(hv.x, hv.y), a0);
                        a1 = ffma2(w[2 * p + 1], make_float2(hv.z, hv.w), a1);
                    }
                    const float v = (a0.x + a0.y) + (a1.x + a1.y) + bias;
                    if (tid < G4) __stcg(&xp_out[(size_t)(t0 + s) * G4 + tid], v);
                    __syncthreads();
                }
            }
            if (tid == 0) {                 // stores ordered by last __syncthreads
                __threadfence();
                *(volatile int*)&g_xpdone[l][k] = 1;
            }
        }
    }
}

// ============================================================================
// FC + softmax + argmax (fully parallel, reads g_h[3])
// ============================================================================
__global__ void fc_k(const float* __restrict__ fcw, const float* __restrict__ fcb,
                     float* __restrict__ out, int T, int out_size)
{
    const int t = blockIdx.x * blockDim.x + threadIdx.x;
    if (t >= T) return;
    const float* hp = &g_h[NL - 1][(size_t)t * H90];
    float l0 = fcb[0], l1 = fcb[1];
    #pragma unroll
    for (int p = 0; p < H90 / 2; p++) {
        const float2 hv = *(const float2*)&hp[2 * p];
        l0 = fmaf(fcw[2 * p],       hv.x, fmaf(fcw[2 * p + 1],       hv.y, l0));
        l1 = fmaf(fcw[H90 + 2 * p], hv.x, fmaf(fcw[H90 + 2 * p + 1], hv.y, l1));
    }
    const float m  = fmaxf(l0, l1);
    const float e0 = __expf(l0 - m), e1 = __expf(l1 - m);
    const float inv = __fdividef(1.f, e0 + e1);
    const float p0 = e0 * inv, p1 = e1 * inv;
    const int   zv = (l1 > l0) ? 1 : 0;   // argmax, first-max-wins on ties

    const long os = (long)out_size;
    if (os >= 2L * T) {
        out[2 * (size_t)t]     = p0;
        out[2 * (size_t)t + 1] = p1;
        if (os >= 3L * T) out[2 * (size_t)T + t] = (float)zv;
    } else {
        ((int*)out)[t] = zv;   // fallback: zv-only int32 output
    }
}

// ============================================================================
extern "C" void kernel_launch(void* const* d_in, const int* in_sizes, int n_in,
                              void* d_out, int out_size)
{
    const float* x    = (const float*)d_in[0];
    const float* h0   = (const float*)d_in[1];
    const float* c0   = (const float*)d_in[2];
    const float* wih0 = (const float*)d_in[3];
    const float* wih1 = (const float*)d_in[4];
    const float* wih2 = (const float*)d_in[5];
    const float* wih3 = (const float*)d_in[6];
    const float* whh  = (const float*)d_in[7];
    const float* bih  = (const float*)d_in[8];
    const float* bhh  = (const float*)d_in[9];
    const float* fcw  = (const float*)d_in[10];
    const float* fcb  = (const float*)d_in[11];

    int T = in_sizes[0] / 6;
    if (T > T_MAX) T = T_MAX;

    init_k<<<(NL * NCHMAX + 255) / 256, 256>>>();
    lstm_main<<<NBLK, NTHREADS>>>(x, h0, c0, wih0, wih1, wih2, wih3,
                                  whh, bih, bhh, T);
    fc_k<<<(T + 255) / 256, 256>>>(fcw, fcb, (float*)d_out, T, out_size);
}

// round 2
// speedup vs baseline: 1.0619x; 1.0619x over previous
#include <cuda_runtime.h>

// ============================================================================
// LSTM_3040836845939: 4-layer LSTM (T=262144, H=90) + FC(2) + softmax + argmax
//
// R2: recurrent step restructured for minimal critical path:
//  - gate nonlinearity applied at the producer thread (MUFU spread on 12 warps)
//  - all 4 gates of hidden index j live in one warp -> __syncwarp exchange
//  - ONE __syncthreads per step (shA double-buffered by step parity)
//  - chunk granularity 256 steps
// ============================================================================

#define T_MAX    262144
#define H90      90
#define HP       92            // H padded to multiple of 4
#define G4       360           // 4*H gate rows
#define NL       4
#define CH       256           // timesteps per pipeline chunk
#define NCHMAX   (T_MAX / CH)  // 1024
#define NBLK     64
#define NTHREADS 384

// -------- static device scratch --------
__device__ float g_xp[NL][(size_t)T_MAX * G4];   // x_proj per layer
__device__ float g_h [NL][(size_t)T_MAX * H90];  // h outputs per layer
__device__ int   g_hdone [NL][NCHMAX];
__device__ int   g_xpdone[NL][NCHMAX];
__device__ int   g_ctr;

// -------- packed fp32x2 FMA --------
__device__ __forceinline__ float2 ffma2(float2 a, float2 b, float2 c) {
#if defined(__CUDA_ARCH__) && (__CUDA_ARCH__ >= 1000)
    unsigned long long ua = *reinterpret_cast<unsigned long long*>(&a);
    unsigned long long ub = *reinterpret_cast<unsigned long long*>(&b);
    unsigned long long uc = *reinterpret_cast<unsigned long long*>(&c);
    unsigned long long ud;
    asm("fma.rn.f32x2 %0, %1, %2, %3;" : "=l"(ud) : "l"(ua), "l"(ub), "l"(uc));
    return *reinterpret_cast<float2*>(&ud);
#else
    return make_float2(fmaf(a.x, b.x, c.x), fmaf(a.y, b.y, c.y));
#endif
}

__device__ __forceinline__ float sigf(float x) {
    return __fdividef(1.0f, 1.0f + __expf(-x));
}
__device__ __forceinline__ float tanhfast(float x) {
    return 1.0f - __fdividef(2.0f, __expf(2.0f * x) + 1.0f);
}

// -------- flag reset --------
__global__ void init_k() {
    int i = blockIdx.x * blockDim.x + threadIdx.x;
    if (i == 0) g_ctr = 0;
    if (i < NL * NCHMAX) {
        ((int*)g_hdone)[i]  = 0;
        ((int*)g_xpdone)[i] = 0;
    }
}

// ============================================================================
__global__ void __launch_bounds__(NTHREADS, 1) lstm_main(
    const float* __restrict__ x,
    const float* __restrict__ h0,
    const float* __restrict__ c0,
    const float* __restrict__ wih0,
    const float* __restrict__ wih1,
    const float* __restrict__ wih2,
    const float* __restrict__ wih3,
    const float* __restrict__ whh,
    const float* __restrict__ bih,
    const float* __restrict__ bhh,
    int T)
{
    const int tid = threadIdx.x;
    const int blk = blockIdx.x;
    const int NCH = (T + CH - 1) / CH;

    __shared__ __align__(16) float shA[2][HP];  // double-buffered h
    __shared__ __align__(16) float shB[HP];     // worker staging
    __shared__ float shG[NTHREADS];             // activated gates, warp-local
    __shared__ int   s_task;

    if (blk < NL) {
        // ---------------- recurrent CTA for layer l ----------------
        const int l    = blk;
        const int w    = tid >> 5;       // warp 0..11
        const int L    = tid & 31;       // lane
        const int jj   = L & 7;
        const int gate = L >> 3;         // 0:i 1:f 2:g 3:o
        const int j    = 8 * w + jj;     // hidden index this lane serves
        const bool jv  = (j < H90);
        const int row  = gate * H90 + (jv ? j : 0);   // gate row in [0,360)
        const bool is_t = (gate == 2);
        // branchless activation constants: out = alpha - beta * 1/(1+e^y)
        // sigmoid: y=-x, alpha=0, beta=-1 ; tanh: y=2x, alpha=1, beta=2
        const float ysc   = is_t ? 2.0f : -1.0f;
        const float alpha = is_t ? 1.0f : 0.0f;
        const float beta  = is_t ? 2.0f : -1.0f;

        // W_hh row for this lane's gate row, padded to 92
        float2 wreg[HP / 2];
        #pragma unroll
        for (int p = 0; p < HP / 2; p++) {
            float a = 0.f, b = 0.f;
            const int k2 = 2 * p;
            if (jv) {
                const float* wr = &whh[((size_t)l * G4 + row) * H90];
                if (k2     < H90) a = wr[k2];
                if (k2 + 1 < H90) b = wr[k2 + 1];
            }
            wreg[p] = make_float2(a, b);
        }
        // c state lives on lanes with gate==0 (L<8), index j
        float c = 0.f;
        if (gate == 0 && jv) c = c0[l * H90 + j];
        if (tid < H90) { shA[0][tid] = h0[l * H90 + tid]; shA[1][tid] = 0.f; }
        if (tid >= H90 && tid < HP) { shA[0][tid] = 0.f; shA[1][tid] = 0.f; }
        __syncthreads();

        float* xp_l = g_xp[l];
        float* h_l  = g_h[l];
        float* shGw = &shG[w * 32];

        for (int k = 0; k < NCH; k++) {
            if (tid == 0) {
                while (*(volatile int*)&g_xpdone[l][k] == 0) __nanosleep(64);
                __threadfence();
            }
            __syncthreads();
            const int t0   = k * CH;
            const int rows = min(CH, T - t0);

            const float* xprow = xp_l + (size_t)t0 * G4 + row;
            float xpc = __ldcg(xprow);
            for (int s = 0; s < rows; s++) {
                // prefetch next step's x_proj
                float xpn = (s + 1 < rows) ? __ldcg(xprow + (size_t)(s + 1) * G4) : 0.f;

                // dot(W_hh[row,:], h) with x_proj folded into accumulator
                const float4* hv4 = (const float4*)shA[(t0 + s) & 1];
                float2 a0 = make_float2(xpc, 0.f);
                #pragma unroll
                for (int p = 0; p < HP / 4; p++) {
                    const float4 hv = hv4[p];
                    a0 = ffma2(wreg[2 * p],     make_float2(hv.x, hv.y), a0);
                    a0 = ffma2(wreg[2 * p + 1], make_float2(hv.z, hv.w), a0);
                }
                const float gv = a0.x + a0.y;
                // activation at producer (branchless sigmoid/tanh)
                const float e = __expf(ysc * gv);
                const float r = __fdividef(1.0f, 1.0f + e);
                shGw[L] = fmaf(-beta, r, alpha);
                __syncwarp();

                if (gate == 0 && jv) {
                    const float gi = shGw[L];
                    const float gf = shGw[L + 8];
                    const float gg = shGw[L + 16];
                    const float go = shGw[L + 24];
                    c = fmaf(gf, c, gi * gg);
                    const float hv = go * tanhfast(c);
                    shA[(t0 + s + 1) & 1][j] = hv;
                    __stcg(&h_l[(size_t)(t0 + s) * H90 + j], hv);
                }
                __syncthreads();
                xpc = xpn;
            }
            if (tid == 0) {
                __threadfence();
                *(volatile int*)&g_hdone[l][k] = 1;
            }
        }
    } else {
        // ---------------- worker CTA: x_proj task pool ----------------
        const int total = NL * NCH;
        float* shW0 = shA[0];
        float* shW1 = shB;
        while (true) {
            if (tid == 0) s_task = atomicAdd(&g_ctr, 1);
            __syncthreads();
            const int task = s_task;
            __syncthreads();
            if (task >= total) break;
            const int k  = task >> 2;
            const int l  = task & 3;
            const int t0 = k * CH;
            const int rows = min(CH, T - t0);

            if (l == 0) {
                float2 w0 = make_float2(0, 0), w1 = w0, w2 = w0;
                float bias = 0.f;
                if (tid < G4) {
                    const float* wr = &wih0[tid * 6];
                    w0 = make_float2(wr[0], wr[1]);
                    w1 = make_float2(wr[2], wr[3]);
                    w2 = make_float2(wr[4], wr[5]);
                    bias = bih[tid] + bhh[tid];
                }
                if (tid < 3) ((float2*)shW0)[tid] = ((const float2*)&x[(size_t)t0 * 6])[tid];
                __syncthreads();
                for (int s = 0; s < rows; s++) {
                    float* cur = (s & 1) ? shW1 : shW0;
                    float* nxt = (s & 1) ? shW0 : shW1;
                    if ((s + 1 < rows) && tid < 3)
                        ((float2*)nxt)[tid] = ((const float2*)&x[(size_t)(t0 + s + 1) * 6])[tid];
                    const float2* xb = (const float2*)cur;
                    float2 a = ffma2(w0, xb[0], make_float2(0, 0));
                    a = ffma2(w1, xb[1], a);
                    a = ffma2(w2, xb[2], a);
                    const float v = a.x + a.y + bias;
                    if (tid < G4) __stcg(&g_xp[0][(size_t)(t0 + s) * G4 + tid], v);
                    __syncthreads();
                }
            } else {
                const float* wih = (l == 1) ? wih1 : ((l == 2) ? wih2 : wih3);
                float2 wk[HP / 2];
                float bias = 0.f;
                #pragma unroll
                for (int p = 0; p < HP / 2; p++) {
                    float a = 0.f, b = 0.f;
                    const int k2 = 2 * p;
                    if (tid < G4) {
                        const float* wr = &wih[(size_t)tid * H90];
                        if (k2     < H90) a = wr[k2];
                        if (k2 + 1 < H90) b = wr[k2 + 1];
                    }
                    wk[p] = make_float2(a, b);
                }
                if (tid < G4) bias = bih[l * G4 + tid] + bhh[l * G4 + tid];
                const float* hsrc = g_h[l - 1];

                if (tid == 0) {
                    while (*(volatile int*)&g_hdone[l - 1][k] == 0) __nanosleep(128);
                    __threadfence();
                }
                __syncthreads();
                if (tid < H90) shW0[tid] = __ldcg(&hsrc[(size_t)t0 * H90 + tid]);
                if (tid >= H90 && tid < HP) { shW0[tid] = 0.f; shW1[tid] = 0.f; }
                __syncthreads();

                float* xp_out = g_xp[l];
                for (int s = 0; s < rows; s++) {
                    float* cur = (s & 1) ? shW1 : shW0;
                    float* nxt = (s & 1) ? shW0 : shW1;
                    if ((s + 1 < rows) && tid < H90)
                        nxt[tid] = __ldcg(&hsrc[(size_t)(t0 + s + 1) * H90 + tid]);
                    float2 a0 = make_float2(0, 0), a1 = a0;
                    #pragma unroll
                    for (int p = 0; p < HP / 4; p++) {
                        const float4 hv = *(const float4*)&cur[4 * p];
                        a0 = ffma2(wk[2 * p],     make_float2(hv.x, hv.y), a0);
                        a1 = ffma2(wk[2 * p + 1], make_float2(hv.z, hv.w), a1);
                    }
                    const float v = (a0.x + a0.y) + (a1.x + a1.y) + bias;
                    if (tid < G4) __stcg(&xp_out[(size_t)(t0 + s) * G4 + tid], v);
                    __syncthreads();
                }
            }
            if (tid == 0) {
                __threadfence();
                *(volatile int*)&g_xpdone[l][k] = 1;
            }
        }
    }
}

// ============================================================================
__global__ void fc_k(const float* __restrict__ fcw, const float* __restrict__ fcb,
                     float* __restrict__ out, int T, int out_size)
{
    const int t = blockIdx.x * blockDim.x + threadIdx.x;
    if (t >= T) return;
    const float* hp = &g_h[NL - 1][(size_t)t * H90];
    float l0 = fcb[0], l1 = fcb[1];
    #pragma unroll
    for (int p = 0; p < H90 / 2; p++) {
        const float2 hv = *(const float2*)&hp[2 * p];
        l0 = fmaf(fcw[2 * p],       hv.x, fmaf(fcw[2 * p + 1],       hv.y, l0));
        l1 = fmaf(fcw[H90 + 2 * p], hv.x, fmaf(fcw[H90 + 2 * p + 1], hv.y, l1));
    }
    const float m  = fmaxf(l0, l1);
    const float e0 = __expf(l0 - m), e1 = __expf(l1 - m);
    const float inv = __fdividef(1.f, e0 + e1);
    const float p0 = e0 * inv, p1 = e1 * inv;
    const int   zv = (l1 > l0) ? 1 : 0;

    const long os = (long)out_size;
    if (os >= 2L * T) {
        out[2 * (size_t)t]     = p0;
        out[2 * (size_t)t + 1] = p1;
        if (os >= 3L * T) out[2 * (size_t)T + t] = (float)zv;
    } else {
        ((int*)out)[t] = zv;
    }
}

// ============================================================================
extern "C" void kernel_launch(void* const* d_in, const int* in_sizes, int n_in,
                              void* d_out, int out_size)
{
    const float* x    = (const float*)d_in[0];
    const float* h0   = (const float*)d_in[1];
    const float* c0   = (const float*)d_in[2];
    const float* wih0 = (const float*)d_in[3];
    const float* wih1 = (const float*)d_in[4];
    const float* wih2 = (const float*)d_in[5];
    const float* wih3 = (const float*)d_in[6];
    const float* whh  = (const float*)d_in[7];
    const float* bih  = (const float*)d_in[8];
    const float* bhh  = (const float*)d_in[9];
    const float* fcw  = (const float*)d_in[10];
    const float* fcb  = (const float*)d_in[11];

    int T = in_sizes[0] / 6;
    if (T > T_MAX) T = T_MAX;

    init_k<<<(NL * NCHMAX + 255) / 256, 256>>>();
    lstm_main<<<NBLK, NTHREADS>>>(x, h0, c0, wih0, wih1, wih2, wih3,
                                  whh, bih, bhh, T);
    fc_k<<<(T + 255) / 256, 256>>>(fcw, fcb, (float*)d_out, T, out_size);
}